// round 5
// baseline (speedup 1.0000x reference)
#include <cuda_runtime.h>
#include <cuda_bf16.h>
#include <stdint.h>

// Exact Euclidean distance transform (matches the Meijster-style reference)
// on a 1536x1536 binary mask.
//
// Kernel 1 (pack): column-packed background bitmap via warp ballot transpose.
//   colbits[w*C + j] bit b == (mask[(w*32+b)*C + j] == 0). 288 KB, L2-resident.
//   One warp per 32x32 tile: 32 coalesced row loads + 32 ballots; no smem.
//
// Kernel 2 (edt, one 512-thread block per row):
//   phase 1: vertical nearest-background. Words (wi-1, wi, wi+1) form two
//     64-bit windows guaranteeing +/-32 rows of coverage for any bit position
//     -> branch-free ffsll/clzll; cross-word expansion is warp-voted and
//     essentially never taken for a random mask (exact fallback kept).
//     Cap 3072 (= R+C) when the column has no background at all.
//   phase 2: horizontal min-plus with exact early exit (t^2 >= best cannot
//     improve since g2 >= 0). Out-of-range neighbors handled by CLAMPING:
//     s[0] at offset t>j gives g2[0]+t^2 >= g2[0]+j^2 (the true candidate
//     already evaluated at t=j), so clamped reads never undercut the exact
//     minimum and no candidate is missed -> exact, zero bounds branches.
//
// All quantities (g^2 <= 3072^2, t^2, sums < 2^24) are integers exactly
// representable in fp32. Final sqrt via x*rsqrt(x) (error ~1e-7 << 1e-3 tol).

#define R_DIM 1536
#define C_DIM 1536
#define W_DIM (R_DIM / 32)     // 48 words per column
#define BIG_I (R_DIM + C_DIM)
#define EDT_T 512              // threads per edt block
#define JPT   (C_DIM / EDT_T)  // 3 columns per thread

__device__ uint32_t g_colbits[W_DIM * C_DIM];

// 8 warps/block, each warp packs one 32x32 tile. grid(6, 48).
__global__ __launch_bounds__(256) void pack_kernel(const float* __restrict__ mask)
{
    const int lane = threadIdx.x & 31;
    const int warp = threadIdx.x >> 5;
    const int col0 = (blockIdx.x * 8 + warp) * 32;
    const int row0 = blockIdx.y * 32;

    const float* p = mask + row0 * C_DIM + col0 + lane;

    uint32_t myword = 0;
    #pragma unroll
    for (int r = 0; r < 32; ++r) {
        const uint32_t b = __ballot_sync(0xffffffffu, p[r * C_DIM] == 0.0f);
        myword |= ((b >> lane) & 1u) << r;
    }
    g_colbits[blockIdx.y * C_DIM + col0 + lane] = myword;
}

__global__ __launch_bounds__(EDT_T) void edt_kernel(float* __restrict__ out)
{
    const int row = blockIdx.x;
    const int tid = threadIdx.x;
    const int wi  = row >> 5;
    const int bi  = row & 31;

    __shared__ float s[C_DIM];

    // ---- phase 1: vertical nearest background, 64-bit windows ----
    const uint32_t* base = g_colbits + wi * C_DIM;
    uint32_t lo[JPT], mid[JPT], hi[JPT];
    #pragma unroll
    for (int u = 0; u < JPT; ++u) {
        const int j = tid + u * EDT_T;
        mid[u] = base[j];
        lo[u]  = (wi > 0)         ? base[j - C_DIM] : 0u;
        hi[u]  = (wi < W_DIM - 1) ? base[j + C_DIM] : 0u;
    }

    #pragma unroll
    for (int u = 0; u < JPT; ++u) {
        const int j = tid + u * EDT_T;

        // dn bit k   = row+k  (k = 0 .. 63-bi)
        // up bit 63-k = row-k (k = 0 .. 32+bi)
        const uint64_t dn = ((((uint64_t)hi[u]  << 32) | mid[u]) >> bi);
        const uint64_t up = ((((uint64_t)mid[u] << 32) | lo[u]) << (31 - bi));

        int best = BIG_I;
        if (dn) best = __ffsll((long long)dn) - 1;
        if (up) best = min(best, __clzll((long long)up));

        // rare exact expansion beyond the guaranteed window (warp-voted)
        const bool need = (best > 63 - bi) || (best > 32 + bi);
        if (__any_sync(0xffffffffu, need)) {
            int wd = wi + 2, dn_off = 64 - bi;
            int wu = wi - 2, up_off = 33 + bi;
            while ((wd < W_DIM && dn_off < best) || (wu >= 0 && up_off < best)) {
                if (wd < W_DIM && dn_off < best) {
                    const uint32_t x = g_colbits[wd * C_DIM + j];
                    if (x) best = min(best, dn_off + __ffs(x) - 1);
                    ++wd; dn_off += 32;
                } else wd = W_DIM;
                if (wu >= 0 && up_off < best) {
                    const uint32_t x = g_colbits[wu * C_DIM + j];
                    if (x) best = min(best, up_off + __clz(x));
                    --wu; up_off += 32;
                } else wu = -1;
            }
        }

        const float g = (float)best;
        s[j] = g * g;
    }

    __syncthreads();

    // ---- phase 2: horizontal windowed min-plus (exact, clamped, checkless) ----
    #pragma unroll
    for (int u = 0; u < JPT; ++u) {
        const int j = tid + u * EDT_T;
        float best = s[j];
        float t2 = 1.0f, inc = 3.0f;   // t^2, then += (2t+1)
        int l = j, r = j;
        #pragma unroll 1
        while (t2 < best) {
            l = max(l - 1, 0);
            r = min(r + 1, C_DIM - 1);
            best = fminf(best, fminf(s[l], s[r]) + t2);
            t2 += inc; inc += 2.0f;
        }
        const float d = (best > 0.0f) ? best * __frsqrt_rn(best) : 0.0f;
        out[row * C_DIM + j] = d;
    }
}

extern "C" void kernel_launch(void* const* d_in, const int* in_sizes, int n_in,
                              void* d_out, int out_size) {
    const float* mask = (const float*)d_in[0];
    float* out = (float*)d_out;

    dim3 pgrid(C_DIM / 256, R_DIM / 32);   // (6, 48), 8 warps each
    pack_kernel<<<pgrid, 256>>>(mask);
    edt_kernel<<<R_DIM, EDT_T>>>(out);
}

// round 6
// speedup vs baseline: 1.1335x; 1.1335x over previous
#include <cuda_runtime.h>
#include <cuda_bf16.h>
#include <stdint.h>

// Exact Euclidean distance transform (matches the Meijster-style reference)
// on a 1536x1536 binary mask.
//
// Kernel 1 (pack): column-packed background bitmap via warp ballot transpose.
//   colbits[w*C + j] bit b == (mask[(w*32+b)*C + j] == 0). 288 KB, L2-resident.
//
// Kernel 2 (edt, one 512-thread block per row):
//   phase 1: vertical nearest-background. bi = row%32 is uniform per block, so
//     load ONE extra word on the weak side only (below if bi<16, above else)
//     and build a 64-bit window there; the strong side uses the 32-bit word.
//     Guaranteed coverage >= 16 rows each way, so the exact word-walk fallback
//     triggers only if best > 16 (P ~ 2^-33 per lane, warp-voted: never taken
//     for a random mask, kept for exactness). Cap 3072 (= R+C).
//   phase 2: horizontal min-plus. Unrolled branch-free t=1,2 window on a
//     sentinel-padded shared row; candidates with t^2 >= best cannot improve
//     (g2 >= 0), so the exact clamped expansion loop from t=3 runs only if
//     __any(best > 9) -- P(no background within distance 3) ~ 2^-29 per lane.
//     Sentinels are BIG^2 (never selected: best <= g2 <= BIG^2 < BIG^2 + t^2).
//     Clamped reads in the fallback give g2[0]+t^2 >= g2[0]+j^2 (the true t=j
//     candidate), so they never undercut the exact minimum.
//
// All quantities (g^2 <= 3072^2, t^2, sums < 2^24) are integers exactly
// representable in fp32. Final sqrt via x*rsqrt(x) (error ~1e-7 << 1e-3 tol).

#define R_DIM 1536
#define C_DIM 1536
#define W_DIM (R_DIM / 32)     // 48 words per column
#define BIG_I (R_DIM + C_DIM)
#define BIGF2 ((float)BIG_I * (float)BIG_I)
#define EDT_T 512              // threads per edt block
#define JPT   (C_DIM / EDT_T)  // 3 columns per thread
#define PAD   4

__device__ uint32_t g_colbits[W_DIM * C_DIM];

// 8 warps/block, each warp packs one 32x32 tile. grid(6, 48).
__global__ __launch_bounds__(256) void pack_kernel(const float* __restrict__ mask)
{
    const int lane = threadIdx.x & 31;
    const int warp = threadIdx.x >> 5;
    const int col0 = (blockIdx.x * 8 + warp) * 32;
    const int row0 = blockIdx.y * 32;

    const float* p = mask + row0 * C_DIM + col0 + lane;

    uint32_t myword = 0;
    #pragma unroll
    for (int r = 0; r < 32; ++r) {
        const uint32_t b = __ballot_sync(0xffffffffu, p[r * C_DIM] == 0.0f);
        myword |= ((b >> lane) & 1u) << r;
    }
    g_colbits[blockIdx.y * C_DIM + col0 + lane] = myword;
}

__global__ __launch_bounds__(EDT_T) void edt_kernel(float* __restrict__ out)
{
    const int row = blockIdx.x;
    const int tid = threadIdx.x;
    const int wi  = row >> 5;
    const int bi  = row & 31;

    __shared__ float g2s[C_DIM + 2 * PAD];
    float* const sp = g2s + PAD;

    if (tid < PAD) {                  // tiny sentinel pads
        g2s[tid] = BIGF2;
        g2s[PAD + C_DIM + tid] = BIGF2;
    }

    // ---- phase 1: vertical nearest background ----
    const bool lowhalf = bi < 16;                      // uniform per block
    const int  extoff  = lowhalf ? -C_DIM : C_DIM;
    const bool have_ext = lowhalf ? (wi > 0) : (wi < W_DIM - 1);
    const uint32_t* base = g_colbits + wi * C_DIM;

    uint32_t mid[JPT], ext[JPT];
    #pragma unroll
    for (int u = 0; u < JPT; ++u) {
        const int j = tid + u * EDT_T;
        mid[u] = base[j];
        ext[u] = have_ext ? base[j + extoff] : 0u;
    }

    #pragma unroll
    for (int u = 0; u < JPT; ++u) {
        const int j = tid + u * EDT_T;
        int best = BIG_I;

        if (lowhalf) {
            // strong up (64-bit: mid over lo), 32-bit down
            const uint64_t up = ((((uint64_t)mid[u]) << 32) | ext[u]) << (31 - bi);
            const uint32_t dn = mid[u] >> bi;
            if (dn) best = __ffs(dn) - 1;
            if (up) best = min(best, __clzll((long long)up));
        } else {
            // strong down (64-bit: hi over mid), 32-bit up
            const uint64_t dn = ((((uint64_t)ext[u]) << 32) | mid[u]) >> bi;
            const uint32_t up = mid[u] << (31 - bi);
            if (dn) best = __ffsll((long long)dn) - 1;
            if (up) best = min(best, __clz(up));
        }

        // exact fallback beyond the >=16-row guaranteed window (never taken
        // for a random mask; warp-voted to stay converged)
        if (__any_sync(0xffffffffu, best > 16)) {
            int wd = wi + 1, dn_off = 32 - bi;
            int wu = wi - 1, up_off = bi + 1;
            while ((wd < W_DIM && dn_off < best) || (wu >= 0 && up_off < best)) {
                if (wd < W_DIM && dn_off < best) {
                    const uint32_t x = g_colbits[wd * C_DIM + j];
                    if (x) best = min(best, dn_off + __ffs(x) - 1);
                    ++wd; dn_off += 32;
                } else wd = W_DIM;
                if (wu >= 0 && up_off < best) {
                    const uint32_t x = g_colbits[wu * C_DIM + j];
                    if (x) best = min(best, up_off + __clz(x));
                    --wu; up_off += 32;
                } else wu = -1;
            }
        }

        const float g = (float)best;
        sp[j] = g * g;
    }

    __syncthreads();

    // ---- phase 2: horizontal min-plus, branch-free t=1,2 + rare fallback ----
    float* const out_row = out + row * C_DIM;
    #pragma unroll
    for (int u = 0; u < JPT; ++u) {
        const int j = tid + u * EDT_T;
        float best = sp[j];
        const float c1 = fminf(sp[j - 1], sp[j + 1]) + 1.0f;
        const float c2 = fminf(sp[j - 2], sp[j + 2]) + 4.0f;
        best = fminf(best, fminf(c1, c2));

        if (__any_sync(0xffffffffu, best > 9.0f)) {
            int t = 3; float t2 = 9.0f, inc = 7.0f;
            while (t2 < best) {
                const int l = max(j - t, 0);
                const int r = min(j + t, C_DIM - 1);
                best = fminf(best, fminf(sp[l], sp[r]) + t2);
                t2 += inc; inc += 2.0f; ++t;
            }
        }

        out_row[j] = (best > 0.0f) ? best * __frsqrt_rn(best) : 0.0f;
    }
}

extern "C" void kernel_launch(void* const* d_in, const int* in_sizes, int n_in,
                              void* d_out, int out_size) {
    const float* mask = (const float*)d_in[0];
    float* out = (float*)d_out;

    dim3 pgrid(C_DIM / 256, R_DIM / 32);   // (6, 48), 8 warps each
    pack_kernel<<<pgrid, 256>>>(mask);
    edt_kernel<<<R_DIM, EDT_T>>>(out);
}

// round 7
// speedup vs baseline: 1.1359x; 1.0021x over previous
#include <cuda_runtime.h>
#include <cuda_bf16.h>
#include <stdint.h>

// Exact Euclidean distance transform (matches the Meijster-style reference)
// on a 1536x1536 binary mask.
//
// Kernel 1 (pack): column-packed background bitmap via warp ballot transpose.
//   colbits[w*C + j] bit b == (mask[(w*32+b)*C + j] == 0). 288 KB, L2-resident.
//
// Kernel 2 (edt): 32-row x 128-col tiles, one thread per column strip.
//   phase 1: sequential Meijster scan over the strip's 32 bitmap bits held in
//     a register (d = bg ? 0 : d+1), carries from the adjacent words via one
//     clz/ffs (exact word-walk for the 2^-32 empty-word case). Cap at 3072
//     (= R+C, the reference's BIG). g^2 stored as int in shared (+2 halo cols
//     computed by lanes 0..3; out-of-image halo = BIG^2 sentinel, never
//     selected since sentinel + t^2 > BIG^2 >= any real candidate).
//   phase 2: exact t=0,1,2 min-plus window from shared; candidates at t>=3
//     can only improve when best > 9 (g2 >= 0), so an exact fallback --
//     recomputing g^2 straight from the bitmap for arbitrary columns -- runs
//     under a warp vote with per-lane probability ~2^-27 (kept for exactness).
//
// All quantities (g^2 <= 3072^2, t^2, sums < 2^24) are integers exactly
// representable in fp32. Final sqrt via x*rsqrt(x) (error ~1e-7 << 1e-3 tol).

#define R_DIM 1536
#define C_DIM 1536
#define W_DIM (R_DIM / 32)
#define BIG_I (R_DIM + C_DIM)       // 3072
#define BIG2  (BIG_I * BIG_I)       // 9437184 < 2^24
#define TC 128                      // tile columns
#define TR 32                       // tile rows (one bitmap word)
#define SSTR (TC + 8)               // shared row stride

__device__ uint32_t g_colbits[W_DIM * C_DIM];

// 8 warps/block, each warp packs one 32x32 tile. grid(6, 48).
__global__ __launch_bounds__(256) void pack_kernel(const float* __restrict__ mask)
{
    const int lane = threadIdx.x & 31;
    const int warp = threadIdx.x >> 5;
    const int col0 = (blockIdx.x * 8 + warp) * 32;
    const int row0 = blockIdx.y * 32;

    const float* p = mask + row0 * C_DIM + col0 + lane;

    uint32_t myword = 0;
    #pragma unroll
    for (int r = 0; r < 32; ++r) {
        const uint32_t b = __ballot_sync(0xffffffffu, p[r * C_DIM] == 0.0f);
        myword |= ((b >> lane) & 1u) << r;
    }
    g_colbits[blockIdx.y * C_DIM + col0 + lane] = myword;
}

// Exact vertical distance^2 at (r, k), straight from the bitmap (rare path).
__device__ __noinline__ int g2_global(int r, int k)
{
    const int wi = r >> 5, bi = r & 31;
    const uint32_t w = g_colbits[wi * C_DIM + k];
    int best = BIG_I;
    const uint32_t dn = w >> bi;
    if (dn) best = __ffs(dn) - 1;
    const uint32_t up = w << (31 - bi);
    if (up) best = min(best, __clz(up));
    int wd = wi + 1, dn_off = 32 - bi;
    int wu = wi - 1, up_off = bi + 1;
    while ((wd < W_DIM && dn_off < best) || (wu >= 0 && up_off < best)) {
        if (wd < W_DIM && dn_off < best) {
            const uint32_t x = g_colbits[wd * C_DIM + k];
            if (x) best = min(best, dn_off + __ffs(x) - 1);
            ++wd; dn_off += 32;
        } else wd = W_DIM;
        if (wu >= 0 && up_off < best) {
            const uint32_t x = g_colbits[wu * C_DIM + k];
            if (x) best = min(best, up_off + __clz(x));
            --wu; up_off += 32;
        } else wu = -1;
    }
    return best * best;
}

// Phase 1 for one column strip: write 32 g^2 ints to sdst[b*SSTR].
__device__ __forceinline__ void phase1_col(int gc, int wi0, int* sdst)
{
    const uint32_t w0 = g_colbits[wi0 * C_DIM + gc];

    // carry from above: distance from row r0-1 to nearest bg at rows <= r0-1
    int du = BIG_I;
    {
        int wu = wi0 - 1, off = 0;
        while (wu >= 0) {
            const uint32_t x = g_colbits[wu * C_DIM + gc];
            if (x) { du = off + __clz(x); break; }
            off += 32; --wu;
        }
    }
    // carry from below: distance from row r0+32 to nearest bg at rows >= r0+32
    int dd = BIG_I;
    {
        int wd = wi0 + 1, off = 0;
        while (wd < W_DIM) {
            const uint32_t x = g_colbits[wd * C_DIM + gc];
            if (x) { dd = off + __ffs(x) - 1; break; }
            off += 32; ++wd;
        }
    }

    int dp[TR];
    int d = du;
    #pragma unroll
    for (int b = 0; b < TR; ++b) {
        d = ((w0 >> b) & 1u) ? 0 : d + 1;
        dp[b] = d;
    }
    d = dd;
    #pragma unroll
    for (int b = TR - 1; b >= 0; --b) {
        d = ((w0 >> b) & 1u) ? 0 : d + 1;
        const int g = min(min(dp[b], d), BIG_I);
        sdst[b * SSTR] = g * g;
    }
}

__global__ __launch_bounds__(TC) void edt_kernel(float* __restrict__ out)
{
    const int tid = threadIdx.x;
    const int c0  = blockIdx.x * TC;
    const int wiy = blockIdx.y;          // strip index; rows [wiy*32, wiy*32+32)
    const int r0  = wiy * TR;

    __shared__ int s[TR * SSTR];

    // own column
    phase1_col(c0 + tid, wiy, &s[tid + 4]);

    // halo columns (2 each side), lanes 0..3 of warp 0 in parallel
    if (tid < 4) {
        const int sc = (tid < 2) ? (2 + tid) : (TC + 4 + (tid - 2));
        const int gc = (tid < 2) ? (c0 - 2 + tid) : (c0 + TC + (tid - 2));
        if (gc >= 0 && gc < C_DIM) {
            phase1_col(gc, wiy, &s[sc]);
        } else {
            #pragma unroll
            for (int b = 0; b < TR; ++b) s[b * SSTR + sc] = BIG2;
        }
    }

    __syncthreads();

    const int jg = c0 + tid;
    #pragma unroll 4
    for (int r = 0; r < TR; ++r) {
        const int* srow = &s[r * SSTR + 4];
        int best = srow[tid];
        const int c1 = min(srow[tid - 1], srow[tid + 1]) + 1;
        const int c2 = min(srow[tid - 2], srow[tid + 2]) + 4;
        best = min(best, min(c1, c2));

        if (__any_sync(0xffffffffu, best > 9)) {     // exact, essentially never
            int t = 3, t2 = 9, inc = 7;
            while (t2 < best) {
                const int kl = jg - t, kr = jg + t;
                if (kl < 0 && kr >= C_DIM) break;
                if (kl >= 0)     best = min(best, g2_global(r0 + r, kl) + t2);
                if (kr < C_DIM)  best = min(best, g2_global(r0 + r, kr) + t2);
                t2 += inc; inc += 2; ++t;
            }
        }

        const float f = (float)best;
        out[(r0 + r) * C_DIM + jg] = best ? f * __frsqrt_rn(f) : 0.0f;
    }
}

extern "C" void kernel_launch(void* const* d_in, const int* in_sizes, int n_in,
                              void* d_out, int out_size) {
    const float* mask = (const float*)d_in[0];
    float* out = (float*)d_out;

    dim3 pgrid(C_DIM / 256, R_DIM / 32);   // (6, 48)
    pack_kernel<<<pgrid, 256>>>(mask);

    dim3 egrid(C_DIM / TC, R_DIM / TR);    // (12, 48)
    edt_kernel<<<egrid, TC>>>(out);
}

// round 8
// speedup vs baseline: 1.2861x; 1.1322x over previous
#include <cuda_runtime.h>
#include <cuda_bf16.h>
#include <stdint.h>

// Exact Euclidean distance transform (matches the Meijster-style reference)
// on a 1536x1536 binary mask.
//
// Kernel 1 (pack): column-packed background bitmap via warp ballot transpose.
//   colbits[w*C + j] bit b == (mask[(w*32+b)*C + j] == 0). 288 KB, L2-resident.
//
// Kernel 2 (edt): 8-row x 256-col tiles, one thread per (column, 8-row strip).
//   1152 blocks x 256 threads = 294912 threads -> ~full occupancy (the R7
//   version used 32-row strips: 4x fewer threads, occ 22.6%, issue-starved).
//   phase 1: Meijster two-pass scan over the strip's 8 bits (d = bg ? 0 : d+1)
//     with carries from the rest of the word via clz/ffs (b0 is block-uniform
//     so those branches don't diverge) and an exact word-walk when the carry
//     crosses words (P ~ 2^-8 per side). Cap at 3072 (= R+C, reference BIG).
//   phase 2: exact t=0,1,2 min-plus window from shared int g^2 (+2 halo cols,
//     out-of-image halo = BIG^2 sentinel, never selected). t>=3 can only
//     improve when best > 9 (g2 >= 0): exact bitmap-based fallback under a
//     warp vote, per-lane P ~ 2^-29.
//
// All quantities (g^2 <= 3072^2, t^2, sums < 2^24) are integers exactly
// representable in fp32. Final sqrt via x*rsqrt(x) (error ~1e-7 << 1e-3 tol).

#define R_DIM 1536
#define C_DIM 1536
#define W_DIM (R_DIM / 32)
#define BIG_I (R_DIM + C_DIM)       // 3072
#define BIG2  (BIG_I * BIG_I)       // 9437184 < 2^24
#define TC 256                      // tile columns
#define TR 8                        // tile rows
#define SSTR (TC + 8)               // shared row stride (ints)

__device__ uint32_t g_colbits[W_DIM * C_DIM];

// 8 warps/block, each warp packs one 32x32 tile. grid(6, 48).
__global__ __launch_bounds__(256) void pack_kernel(const float* __restrict__ mask)
{
    const int lane = threadIdx.x & 31;
    const int warp = threadIdx.x >> 5;
    const int col0 = (blockIdx.x * 8 + warp) * 32;
    const int row0 = blockIdx.y * 32;

    const float* p = mask + row0 * C_DIM + col0 + lane;

    uint32_t myword = 0;
    #pragma unroll
    for (int r = 0; r < 32; ++r) {
        const uint32_t b = __ballot_sync(0xffffffffu, p[r * C_DIM] == 0.0f);
        myword |= ((b >> lane) & 1u) << r;
    }
    g_colbits[blockIdx.y * C_DIM + col0 + lane] = myword;
}

// Exact vertical distance^2 at (r, k), straight from the bitmap (rare path).
__device__ __noinline__ int g2_global(int r, int k)
{
    const int wi = r >> 5, bi = r & 31;
    const uint32_t w = g_colbits[wi * C_DIM + k];
    int best = BIG_I;
    const uint32_t dn = w >> bi;
    if (dn) best = __ffs(dn) - 1;
    const uint32_t up = w << (31 - bi);
    if (up) best = min(best, __clz(up));
    int wd = wi + 1, dn_off = 32 - bi;
    int wu = wi - 1, up_off = bi + 1;
    while ((wd < W_DIM && dn_off < best) || (wu >= 0 && up_off < best)) {
        if (wd < W_DIM && dn_off < best) {
            const uint32_t x = g_colbits[wd * C_DIM + k];
            if (x) best = min(best, dn_off + __ffs(x) - 1);
            ++wd; dn_off += 32;
        } else wd = W_DIM;
        if (wu >= 0 && up_off < best) {
            const uint32_t x = g_colbits[wu * C_DIM + k];
            if (x) best = min(best, up_off + __clz(x));
            --wu; up_off += 32;
        } else wu = -1;
    }
    return best * best;
}

// Phase 1 for one 8-row column strip: write g^2 ints to sdst[b*SSTR].
// wi = word index, b0 = bit offset of strip's first row within the word
// (b0 is uniform per block -> no divergence on its branches).
__device__ __forceinline__ void phase1_strip(int gc, int wi, int b0, int* sdst)
{
    const uint32_t w = g_colbits[wi * C_DIM + gc];

    // carry from above: distance from row r0-1 to nearest bg at rows <= r0-1
    const uint32_t upbits = b0 ? (w << (32 - b0)) : 0u;   // bit31 == row r0-1
    int du;
    if (upbits) {
        du = __clz(upbits);
    } else {
        du = BIG_I;
        int wu = wi - 1, off = b0;
        while (wu >= 0) {
            const uint32_t x = g_colbits[wu * C_DIM + gc];
            if (x) { du = off + __clz(x); break; }
            off += 32; --wu;
        }
    }

    // carry from below: distance from row r0+8 to nearest bg at rows >= r0+8
    const int sh = b0 + TR;
    const uint32_t dnbits = (sh < 32) ? (w >> sh) : 0u;   // bit0 == row r0+8
    int dd;
    if (dnbits) {
        dd = __ffs(dnbits) - 1;
    } else {
        dd = BIG_I;
        int wd = wi + 1, off = 24 - b0;   // 32 - (b0+8)
        while (wd < W_DIM) {
            const uint32_t x = g_colbits[wd * C_DIM + gc];
            if (x) { dd = off + __ffs(x) - 1; break; }
            off += 32; ++wd;
        }
    }

    int dp[TR];
    int d = du;
    #pragma unroll
    for (int b = 0; b < TR; ++b) {
        d = ((w >> (b0 + b)) & 1u) ? 0 : d + 1;
        dp[b] = d;
    }
    d = dd;
    #pragma unroll
    for (int b = TR - 1; b >= 0; --b) {
        d = ((w >> (b0 + b)) & 1u) ? 0 : d + 1;
        const int g = min(min(dp[b], d), BIG_I);
        sdst[b * SSTR] = g * g;
    }
}

__global__ __launch_bounds__(TC) void edt_kernel(float* __restrict__ out)
{
    const int tid = threadIdx.x;
    const int c0  = blockIdx.x * TC;
    const int r0  = blockIdx.y * TR;
    const int wi  = r0 >> 5;
    const int b0  = r0 & 31;             // in {0,8,16,24}, block-uniform

    __shared__ int s[TR * SSTR];

    // own column
    phase1_strip(c0 + tid, wi, b0, &s[tid + 4]);

    // halo columns (2 each side), lanes 0..3
    if (tid < 4) {
        const int sc = (tid < 2) ? (2 + tid) : (TC + 4 + (tid - 2));
        const int gc = (tid < 2) ? (c0 - 2 + tid) : (c0 + TC + (tid - 2));
        if (gc >= 0 && gc < C_DIM) {
            phase1_strip(gc, wi, b0, &s[sc]);
        } else {
            #pragma unroll
            for (int b = 0; b < TR; ++b) s[b * SSTR + sc] = BIG2;
        }
    }

    __syncthreads();

    const int jg = c0 + tid;
    #pragma unroll
    for (int r = 0; r < TR; ++r) {
        const int* srow = &s[r * SSTR + 4];
        int best = srow[tid];
        const int c1 = min(srow[tid - 1], srow[tid + 1]) + 1;
        const int c2 = min(srow[tid - 2], srow[tid + 2]) + 4;
        best = min(best, min(c1, c2));

        if (__any_sync(0xffffffffu, best > 9)) {     // exact, essentially never
            int t = 3, t2 = 9, inc = 7;
            while (t2 < best) {
                const int kl = jg - t, kr = jg + t;
                if (kl < 0 && kr >= C_DIM) break;
                if (kl >= 0)     best = min(best, g2_global(r0 + r, kl) + t2);
                if (kr < C_DIM)  best = min(best, g2_global(r0 + r, kr) + t2);
                t2 += inc; inc += 2; ++t;
            }
        }

        const float f = (float)best;
        out[(r0 + r) * C_DIM + jg] = best ? f * __frsqrt_rn(f) : 0.0f;
    }
}

extern "C" void kernel_launch(void* const* d_in, const int* in_sizes, int n_in,
                              void* d_out, int out_size) {
    const float* mask = (const float*)d_in[0];
    float* out = (float*)d_out;

    dim3 pgrid(C_DIM / 256, R_DIM / 32);   // (6, 48)
    pack_kernel<<<pgrid, 256>>>(mask);

    dim3 egrid(C_DIM / TC, R_DIM / TR);    // (6, 192)
    edt_kernel<<<egrid, TC>>>(out);
}

// round 9
// speedup vs baseline: 1.3113x; 1.0196x over previous
#include <cuda_runtime.h>
#include <cuda_bf16.h>
#include <stdint.h>

// Exact Euclidean distance transform (matches the Meijster-style reference)
// on a 1536x1536 binary mask.
//
// Kernel 1 (pack): column-packed background bitmap via warp ballot transpose.
//   colbits[w*C + j] bit b == (mask[(w*32+b)*C + j] == 0). 288 KB, L2-resident.
//   All 32 row loads are issued BEFORE the ballots (MLP=32): interleaving
//   load/ballot serializes on the warp sync and makes the kernel latency-bound.
//
// Kernel 2 (edt): 8-row x 256-col tiles, one thread per (column, 8-row strip).
//   phase 1: Meijster two-pass scan over the strip's 8 bits (d = bg ? 0 : d+1)
//     with carries from the rest of the word via clz/ffs (b0 block-uniform ->
//     no divergence) and an exact word-walk when the carry crosses words.
//     Cap at 3072 (= R+C, reference BIG).
//   phase 2: exact min-plus with escalating windows. t=1 always; t=2 only if
//     __any(best > 4) (t^2 >= best cannot improve, g2 >= 0; per-lane
//     P ~ 2^-13); t>=3 exact bitmap fallback only if __any(best > 9)
//     (per-lane P ~ 2^-29). Out-of-image halo = BIG^2 sentinel (never
//     selected: sentinel + t^2 > BIG^2 >= any real candidate).
//
// All quantities (g^2 <= 3072^2, t^2, sums < 2^24) are integers exactly
// representable in fp32. Final sqrt via x*rsqrt(x) (error ~1e-7 << 1e-3 tol).

#define R_DIM 1536
#define C_DIM 1536
#define W_DIM (R_DIM / 32)
#define BIG_I (R_DIM + C_DIM)       // 3072
#define BIG2  (BIG_I * BIG_I)       // 9437184 < 2^24
#define TC 256                      // tile columns
#define TR 8                        // tile rows
#define SSTR (TC + 8)               // shared row stride (ints)

__device__ uint32_t g_colbits[W_DIM * C_DIM];

// 8 warps/block, each warp packs one 32x32 tile. grid(6, 48).
__global__ __launch_bounds__(256) void pack_kernel(const float* __restrict__ mask)
{
    const int lane = threadIdx.x & 31;
    const int warp = threadIdx.x >> 5;
    const int col0 = (blockIdx.x * 8 + warp) * 32;
    const int row0 = blockIdx.y * 32;

    const float* p = mask + row0 * C_DIM + col0 + lane;

    // batch ALL loads first: 32 independent lines in flight (MLP=32)
    float v[32];
    #pragma unroll
    for (int r = 0; r < 32; ++r) v[r] = p[r * C_DIM];

    uint32_t myword = 0;
    #pragma unroll
    for (int r = 0; r < 32; ++r) {
        const uint32_t b = __ballot_sync(0xffffffffu, v[r] == 0.0f);
        myword |= ((b >> lane) & 1u) << r;
    }
    g_colbits[blockIdx.y * C_DIM + col0 + lane] = myword;
}

// Exact vertical distance^2 at (r, k), straight from the bitmap (rare path).
__device__ __noinline__ int g2_global(int r, int k)
{
    const int wi = r >> 5, bi = r & 31;
    const uint32_t w = g_colbits[wi * C_DIM + k];
    int best = BIG_I;
    const uint32_t dn = w >> bi;
    if (dn) best = __ffs(dn) - 1;
    const uint32_t up = w << (31 - bi);
    if (up) best = min(best, __clz(up));
    int wd = wi + 1, dn_off = 32 - bi;
    int wu = wi - 1, up_off = bi + 1;
    while ((wd < W_DIM && dn_off < best) || (wu >= 0 && up_off < best)) {
        if (wd < W_DIM && dn_off < best) {
            const uint32_t x = g_colbits[wd * C_DIM + k];
            if (x) best = min(best, dn_off + __ffs(x) - 1);
            ++wd; dn_off += 32;
        } else wd = W_DIM;
        if (wu >= 0 && up_off < best) {
            const uint32_t x = g_colbits[wu * C_DIM + k];
            if (x) best = min(best, up_off + __clz(x));
            --wu; up_off += 32;
        } else wu = -1;
    }
    return best * best;
}

// Phase 1 for one 8-row column strip: write g^2 ints to sdst[b*SSTR].
__device__ __forceinline__ void phase1_strip(int gc, int wi, int b0, int* sdst)
{
    const uint32_t w = g_colbits[wi * C_DIM + gc];

    // carry from above: distance from row r0-1 to nearest bg at rows <= r0-1
    const uint32_t upbits = b0 ? (w << (32 - b0)) : 0u;   // bit31 == row r0-1
    int du;
    if (upbits) {
        du = __clz(upbits);
    } else {
        du = BIG_I;
        int wu = wi - 1, off = b0;
        while (wu >= 0) {
            const uint32_t x = g_colbits[wu * C_DIM + gc];
            if (x) { du = off + __clz(x); break; }
            off += 32; --wu;
        }
    }

    // carry from below: distance from row r0+8 to nearest bg at rows >= r0+8
    const int sh = b0 + TR;
    const uint32_t dnbits = (sh < 32) ? (w >> sh) : 0u;   // bit0 == row r0+8
    int dd;
    if (dnbits) {
        dd = __ffs(dnbits) - 1;
    } else {
        dd = BIG_I;
        int wd = wi + 1, off = 24 - b0;   // 32 - (b0+8)
        while (wd < W_DIM) {
            const uint32_t x = g_colbits[wd * C_DIM + gc];
            if (x) { dd = off + __ffs(x) - 1; break; }
            off += 32; ++wd;
        }
    }

    int dp[TR];
    int d = du;
    #pragma unroll
    for (int b = 0; b < TR; ++b) {
        d = ((w >> (b0 + b)) & 1u) ? 0 : d + 1;
        dp[b] = d;
    }
    d = dd;
    #pragma unroll
    for (int b = TR - 1; b >= 0; --b) {
        d = ((w >> (b0 + b)) & 1u) ? 0 : d + 1;
        const int g = min(min(dp[b], d), BIG_I);
        sdst[b * SSTR] = g * g;
    }
}

__global__ __launch_bounds__(TC) void edt_kernel(float* __restrict__ out)
{
    const int tid = threadIdx.x;
    const int c0  = blockIdx.x * TC;
    const int r0  = blockIdx.y * TR;
    const int wi  = r0 >> 5;
    const int b0  = r0 & 31;             // in {0,8,16,24}, block-uniform

    __shared__ int s[TR * SSTR];

    // own column
    phase1_strip(c0 + tid, wi, b0, &s[tid + 4]);

    // halo columns (2 each side), lanes 0..3
    if (tid < 4) {
        const int sc = (tid < 2) ? (2 + tid) : (TC + 4 + (tid - 2));
        const int gc = (tid < 2) ? (c0 - 2 + tid) : (c0 + TC + (tid - 2));
        if (gc >= 0 && gc < C_DIM) {
            phase1_strip(gc, wi, b0, &s[sc]);
        } else {
            #pragma unroll
            for (int b = 0; b < TR; ++b) s[b * SSTR + sc] = BIG2;
        }
    }

    __syncthreads();

    const int jg = c0 + tid;
    #pragma unroll
    for (int r = 0; r < TR; ++r) {
        const int* srow = &s[r * SSTR + 4];
        int best = srow[tid];
        best = min(best, min(srow[tid - 1], srow[tid + 1]) + 1);

        // t=2 can only improve when best > 4 (rare: per-lane P ~ 2^-13)
        if (__any_sync(0xffffffffu, best > 4)) {
            best = min(best, min(srow[tid - 2], srow[tid + 2]) + 4);

            // t>=3 can only improve when best > 9 (per-lane P ~ 2^-29)
            if (__any_sync(0xffffffffu, best > 9)) {
                int t = 3, t2 = 9, inc = 7;
                while (t2 < best) {
                    const int kl = jg - t, kr = jg + t;
                    if (kl < 0 && kr >= C_DIM) break;
                    if (kl >= 0)     best = min(best, g2_global(r0 + r, kl) + t2);
                    if (kr < C_DIM)  best = min(best, g2_global(r0 + r, kr) + t2);
                    t2 += inc; inc += 2; ++t;
                }
            }
        }

        const float f = (float)best;
        out[(r0 + r) * C_DIM + jg] = best ? f * __frsqrt_rn(f) : 0.0f;
    }
}

extern "C" void kernel_launch(void* const* d_in, const int* in_sizes, int n_in,
                              void* d_out, int out_size) {
    const float* mask = (const float*)d_in[0];
    float* out = (float*)d_out;

    dim3 pgrid(C_DIM / 256, R_DIM / 32);   // (6, 48)
    pack_kernel<<<pgrid, 256>>>(mask);

    dim3 egrid(C_DIM / TC, R_DIM / TR);    // (6, 192)
    edt_kernel<<<egrid, TC>>>(out);
}

// round 10
// speedup vs baseline: 1.3375x; 1.0200x over previous
#include <cuda_runtime.h>
#include <cuda_bf16.h>
#include <stdint.h>

// Exact Euclidean distance transform (matches the Meijster-style reference)
// on a 1536x1536 binary mask.
//
// Kernel 1 (pack): column-packed background bitmap via warp ballot transpose.
//   colbits[w*C + j] bit b == (mask[(w*32+b)*C + j] == 0). 288 KB, L2-resident.
//   All 32 row loads issued before the ballots (MLP=32).
//
// Kernel 2 (edt): 8-row x 256-col tiles, one thread per (column, 8-row strip).
//   phase 1: Meijster two-pass scan over the strip's 8 bits (d = bg ? 0 : d+1)
//     with carries from the rest of the word via clz/ffs (b0 block-uniform ->
//     no divergence) and an exact word-walk when the carry crosses words.
//     Cap at 3072 (= R+C, reference BIG). g^2 kept in REGISTERS for the own
//     column and mirrored to shared for neighbors.
//   phase 2: exact min-plus with escalating windows. t=1 always (2 LDS);
//     own value from registers. ONE warp vote per strip on max(best[r]) gates
//     t=2 (t^2 >= best cannot improve, g2 >= 0; per-lane-row P ~ 2^-13), and
//     a nested vote gates the exact t>=3 bitmap fallback (P ~ 2^-29).
//     Out-of-image halo = BIG^2 sentinel (never selected).
//
// All quantities (g^2 <= 3072^2, t^2, sums < 2^24) are integers exactly
// representable in fp32. Final sqrt via x*rsqrt(x) (error ~1e-7 << 1e-3 tol).

#define R_DIM 1536
#define C_DIM 1536
#define W_DIM (R_DIM / 32)
#define BIG_I (R_DIM + C_DIM)       // 3072
#define BIG2  (BIG_I * BIG_I)       // 9437184 < 2^24
#define TC 256                      // tile columns
#define TR 8                        // tile rows
#define SSTR (TC + 8)               // shared row stride (ints)

__device__ uint32_t g_colbits[W_DIM * C_DIM];

// 8 warps/block, each warp packs one 32x32 tile. grid(6, 48).
__global__ __launch_bounds__(256) void pack_kernel(const float* __restrict__ mask)
{
    const int lane = threadIdx.x & 31;
    const int warp = threadIdx.x >> 5;
    const int col0 = (blockIdx.x * 8 + warp) * 32;
    const int row0 = blockIdx.y * 32;

    const float* p = mask + row0 * C_DIM + col0 + lane;

    float v[32];
    #pragma unroll
    for (int r = 0; r < 32; ++r) v[r] = p[r * C_DIM];

    uint32_t myword = 0;
    #pragma unroll
    for (int r = 0; r < 32; ++r) {
        const uint32_t b = __ballot_sync(0xffffffffu, v[r] == 0.0f);
        myword |= ((b >> lane) & 1u) << r;
    }
    g_colbits[blockIdx.y * C_DIM + col0 + lane] = myword;
}

// Exact vertical distance^2 at (r, k), straight from the bitmap (rare path).
__device__ __noinline__ int g2_global(int r, int k)
{
    const int wi = r >> 5, bi = r & 31;
    const uint32_t w = g_colbits[wi * C_DIM + k];
    int best = BIG_I;
    const uint32_t dn = w >> bi;
    if (dn) best = __ffs(dn) - 1;
    const uint32_t up = w << (31 - bi);
    if (up) best = min(best, __clz(up));
    int wd = wi + 1, dn_off = 32 - bi;
    int wu = wi - 1, up_off = bi + 1;
    while ((wd < W_DIM && dn_off < best) || (wu >= 0 && up_off < best)) {
        if (wd < W_DIM && dn_off < best) {
            const uint32_t x = g_colbits[wd * C_DIM + k];
            if (x) best = min(best, dn_off + __ffs(x) - 1);
            ++wd; dn_off += 32;
        } else wd = W_DIM;
        if (wu >= 0 && up_off < best) {
            const uint32_t x = g_colbits[wu * C_DIM + k];
            if (x) best = min(best, up_off + __clz(x));
            --wu; up_off += 32;
        } else wu = -1;
    }
    return best * best;
}

// Phase 1 for one 8-row column strip. Writes g^2 to sdst[b*SSTR]; if greg
// is non-null also keeps the values in the caller's register array.
__device__ __forceinline__ void phase1_strip(int gc, int wi, int b0,
                                             int* sdst, int* greg)
{
    const uint32_t w = g_colbits[wi * C_DIM + gc];

    // carry from above: distance from row r0-1 to nearest bg at rows <= r0-1
    const uint32_t upbits = b0 ? (w << (32 - b0)) : 0u;   // bit31 == row r0-1
    int du;
    if (upbits) {
        du = __clz(upbits);
    } else {
        du = BIG_I;
        int wu = wi - 1, off = b0;
        while (wu >= 0) {
            const uint32_t x = g_colbits[wu * C_DIM + gc];
            if (x) { du = off + __clz(x); break; }
            off += 32; --wu;
        }
    }

    // carry from below: distance from row r0+8 to nearest bg at rows >= r0+8
    const int sh = b0 + TR;
    const uint32_t dnbits = (sh < 32) ? (w >> sh) : 0u;   // bit0 == row r0+8
    int dd;
    if (dnbits) {
        dd = __ffs(dnbits) - 1;
    } else {
        dd = BIG_I;
        int wd = wi + 1, off = 24 - b0;   // 32 - (b0+8)
        while (wd < W_DIM) {
            const uint32_t x = g_colbits[wd * C_DIM + gc];
            if (x) { dd = off + __ffs(x) - 1; break; }
            off += 32; ++wd;
        }
    }

    int dp[TR];
    int d = du;
    #pragma unroll
    for (int b = 0; b < TR; ++b) {
        d = ((w >> (b0 + b)) & 1u) ? 0 : d + 1;
        dp[b] = d;
    }
    d = dd;
    #pragma unroll
    for (int b = TR - 1; b >= 0; --b) {
        d = ((w >> (b0 + b)) & 1u) ? 0 : d + 1;
        const int g  = min(min(dp[b], d), BIG_I);
        const int g2 = g * g;
        sdst[b * SSTR] = g2;
        if (greg) greg[b] = g2;
    }
}

__global__ __launch_bounds__(TC) void edt_kernel(float* __restrict__ out)
{
    const int tid = threadIdx.x;
    const int c0  = blockIdx.x * TC;
    const int r0  = blockIdx.y * TR;
    const int wi  = r0 >> 5;
    const int b0  = r0 & 31;             // in {0,8,16,24}, block-uniform

    __shared__ int s[TR * SSTR];
    int g2r[TR];

    // own column (keeps g^2 in registers too)
    phase1_strip(c0 + tid, wi, b0, &s[tid + 4], g2r);

    // halo columns (2 each side), lanes 0..3
    if (tid < 4) {
        const int sc = (tid < 2) ? (2 + tid) : (TC + 4 + (tid - 2));
        const int gc = (tid < 2) ? (c0 - 2 + tid) : (c0 + TC + (tid - 2));
        if (gc >= 0 && gc < C_DIM) {
            phase1_strip(gc, wi, b0, &s[sc], (int*)0);
        } else {
            #pragma unroll
            for (int b = 0; b < TR; ++b) s[b * SSTR + sc] = BIG2;
        }
    }

    __syncthreads();

    const int jg = c0 + tid;

    // t=0,1 window for all rows; own value from registers
    int best[TR];
    int mx = 0;
    #pragma unroll
    for (int r = 0; r < TR; ++r) {
        const int* srow = &s[r * SSTR + 4];
        best[r] = min(g2r[r], min(srow[tid - 1], srow[tid + 1]) + 1);
        mx = max(mx, best[r]);
    }

    // single vote gates the rare t>=2 path for the whole strip
    if (__any_sync(0xffffffffu, mx > 4)) {
        #pragma unroll
        for (int r = 0; r < TR; ++r) {
            const int* srow = &s[r * SSTR + 4];
            int b = best[r];
            b = min(b, min(srow[tid - 2], srow[tid + 2]) + 4);
            if (__any_sync(0xffffffffu, b > 9)) {    // exact t>=3 fallback
                int t = 3, t2 = 9, inc = 7;
                while (t2 < b) {
                    const int kl = jg - t, kr = jg + t;
                    if (kl < 0 && kr >= C_DIM) break;
                    if (kl >= 0)     b = min(b, g2_global(r0 + r, kl) + t2);
                    if (kr < C_DIM)  b = min(b, g2_global(r0 + r, kr) + t2);
                    t2 += inc; inc += 2; ++t;
                }
            }
            best[r] = b;
        }
    }

    // batched epilogue: independent convert/rsqrt/store chains
    #pragma unroll
    for (int r = 0; r < TR; ++r) {
        const float f = (float)best[r];
        out[(r0 + r) * C_DIM + jg] = best[r] ? f * __frsqrt_rn(f) : 0.0f;
    }
}

extern "C" void kernel_launch(void* const* d_in, const int* in_sizes, int n_in,
                              void* d_out, int out_size) {
    const float* mask = (const float*)d_in[0];
    float* out = (float*)d_out;

    dim3 pgrid(C_DIM / 256, R_DIM / 32);   // (6, 48)
    pack_kernel<<<pgrid, 256>>>(mask);

    dim3 egrid(C_DIM / TC, R_DIM / TR);    // (6, 192)
    edt_kernel<<<egrid, TC>>>(out);
}

// round 11
// speedup vs baseline: 1.3824x; 1.0336x over previous
#include <cuda_runtime.h>
#include <cuda_bf16.h>
#include <stdint.h>

// Exact Euclidean distance transform (matches the Meijster-style reference)
// on a 1536x1536 binary mask.
//
// Kernel 1 (pack): column-packed background bitmap via warp ballot transpose
//   into a zero-PADDED array (4 guard columns each side, 1 guard word-row
//   top/bottom). colbits[wi][j] bit b == (mask[(wi*32+b)*C + j] == 0).
//   Pads stay zero (device globals are zero-initialized; pack never writes
//   them), so out-of-image probes read "no background" with NO bounds checks.
//
// Kernel 2 (edt): one thread per (column, 32-row word). Bit-parallel 2D
//   neighborhood search: all integer d^2 <= 9 levels {0,1,2,4,5,8,9} are
//   computed for 32 rows at once from 17 bitmap words via OR/funnel-shift:
//     D(dx,dy) coverage masks ->
//       D1 = sv(c0,1)|c1      D2 = sv(c1,1)       D4 = sv(c0,2)|c2
//       D5 = sv(c1,2)|sv(c2,1)  D8 = sv(c2,2)     D9 = sv(c0,3)|c3
//   where ck = col(j-k)|col(j+k) and sv shifts vertically +/-k across word
//   boundaries. A priority-exclusive pass packs d^2 into 4 bit-planes; each
//   row's output is a few BFE/IMAD + rsqrt. Rows with d^2 > 9 (P ~ 2^-29 per
//   pixel for a random mask) fall to an exact bitmap walk under a warp vote,
//   reproducing the reference's BIG = R+C cap. Exact for ANY input.
//
// All quantities (g^2 <= 3072^2, t^2, sums < 2^24) are integers exactly
// representable in fp32. sqrt via x*rsqrt(x) (error ~1e-7 << 1e-3 tol).

#define R_DIM 1536
#define C_DIM 1536
#define W_DIM (R_DIM / 32)          // 48 word-rows
#define BIG_I (R_DIM + C_DIM)       // 3072
#define CPAD  (C_DIM + 8)           // 4 guard cols each side
#define NROWS (W_DIM + 2)           // 1 guard word-row top/bottom

__device__ uint32_t g_colbits[NROWS * CPAD];   // zero-initialized; pads stay 0

__device__ __forceinline__ const uint32_t* cb_at(int wi, int j) {
    return &g_colbits[(wi + 1) * CPAD + 4 + j];
}

// 8 warps/block, each warp packs one 32x32 tile. grid(6, 48).
__global__ __launch_bounds__(256) void pack_kernel(const float* __restrict__ mask)
{
    const int lane = threadIdx.x & 31;
    const int warp = threadIdx.x >> 5;
    const int col0 = (blockIdx.x * 8 + warp) * 32;
    const int row0 = blockIdx.y * 32;

    const float* p = mask + row0 * C_DIM + col0 + lane;

    float v[32];
    #pragma unroll
    for (int r = 0; r < 32; ++r) v[r] = p[r * C_DIM];

    uint32_t myword = 0;
    #pragma unroll
    for (int r = 0; r < 32; ++r) {
        const uint32_t b = __ballot_sync(0xffffffffu, v[r] == 0.0f);
        myword |= ((b >> lane) & 1u) << r;
    }
    g_colbits[(blockIdx.y + 1) * CPAD + 4 + col0 + lane] = myword;
}

// Exact vertical distance^2 at (r, k) from the bitmap (rare path).
__device__ __noinline__ int g2_global(int r, int k)
{
    const int wi = r >> 5, bi = r & 31;
    const uint32_t w = *cb_at(wi, k);
    int best = BIG_I;
    const uint32_t dn = w >> bi;
    if (dn) best = __ffs(dn) - 1;
    const uint32_t up = w << (31 - bi);
    if (up) best = min(best, __clz(up));
    int wd = wi + 1, dn_off = 32 - bi;
    int wu = wi - 1, up_off = bi + 1;
    while ((wd < W_DIM && dn_off < best) || (wu >= 0 && up_off < best)) {
        if (wd < W_DIM && dn_off < best) {
            const uint32_t x = *cb_at(wd, k);
            if (x) best = min(best, dn_off + __ffs(x) - 1);
            ++wd; dn_off += 32;
        } else wd = W_DIM;
        if (wu >= 0 && up_off < best) {
            const uint32_t x = *cb_at(wu, k);
            if (x) best = min(best, up_off + __clz(x));
            --wu; up_off += 32;
        } else wu = -1;
    }
    return best * best;
}

// vertical +/-k shift across word boundaries: bit b set if (row +- k) set
__device__ __forceinline__ uint32_t sv(uint32_t w, uint32_t prev, uint32_t next, int k)
{
    return __funnelshift_r(w, next, k) | __funnelshift_l(prev, w, k);
}

__global__ __launch_bounds__(256) void edt_kernel(float* __restrict__ out)
{
    const int tid = threadIdx.x;
    const int j   = blockIdx.x * 256 + tid;
    const int wi  = blockIdx.y;

    const uint32_t* W = cb_at(wi, j);
    const uint32_t* P = W - CPAD;
    const uint32_t* N = W + CPAD;

    // 17 word loads (pads make all of them branch-free)
    const uint32_t c0 = W[0];
    const uint32_t c1 = W[-1] | W[1];
    const uint32_t c2 = W[-2] | W[2];
    const uint32_t c3 = W[-3] | W[3];
    const uint32_t p0 = P[0];
    const uint32_t p1 = P[-1] | P[1];
    const uint32_t p2 = P[-2] | P[2];
    const uint32_t n0 = N[0];
    const uint32_t n1 = N[-1] | N[1];
    const uint32_t n2 = N[-2] | N[2];

    // coverage masks per d^2 level (32 rows at once)
    const uint32_t D1 = sv(c0, p0, n0, 1) | c1;
    const uint32_t D2 = sv(c1, p1, n1, 1);
    const uint32_t D4 = sv(c0, p0, n0, 2) | c2;
    const uint32_t D5 = sv(c1, p1, n1, 2) | sv(c2, p2, n2, 1);
    const uint32_t D8 = sv(c2, p2, n2, 2);
    const uint32_t D9 = sv(c0, p0, n0, 3) | c3;

    // priority-exclusive masks -> 4 bit-planes of d^2
    uint32_t cum = c0;
    const uint32_t E1 = D1 & ~cum;  cum |= D1;
    const uint32_t E2 = D2 & ~cum;  cum |= D2;
    const uint32_t E4 = D4 & ~cum;  cum |= D4;
    const uint32_t E5 = D5 & ~cum;  cum |= D5;
    const uint32_t E8 = D8 & ~cum;  cum |= D8;
    const uint32_t E9 = D9 & ~cum;  cum |= D9;

    const uint32_t P0 = E1 | E5 | E9;   // d^2 bit0
    const uint32_t P1 = E2;             // d^2 bit1
    const uint32_t P2 = E4 | E5;        // d^2 bit2
    const uint32_t P3 = E8 | E9;        // d^2 bit3

    float* orow = out + (wi * 32) * C_DIM + j;
    #pragma unroll
    for (int r = 0; r < 32; ++r) {
        const int d2 = ((P0 >> r) & 1) | (((P1 >> r) & 1) << 1)
                     | (((P2 >> r) & 1) << 2) | (((P3 >> r) & 1) << 3);
        const float f = (float)d2;
        orow[r * C_DIM] = d2 ? f * __frsqrt_rn(f) : 0.0f;
    }

    // exact fallback for rows with d^2 > 9 (essentially never taken)
    uint32_t uncov = ~cum;
    if (__any_sync(0xffffffffu, uncov != 0u)) {
        while (uncov) {
            const int b = __ffs(uncov) - 1;
            uncov &= uncov - 1;
            const int row = wi * 32 + b;
            int best = g2_global(row, j);
            int t = 1, t2 = 1, inc = 3;
            while (t2 < best) {
                const int kl = j - t, kr = j + t;
                if (kl < 0 && kr >= C_DIM) break;
                if (kl >= 0)     best = min(best, g2_global(row, kl) + t2);
                if (kr < C_DIM)  best = min(best, g2_global(row, kr) + t2);
                t2 += inc; inc += 2; ++t;
            }
            const float f = (float)best;
            orow[b * C_DIM] = best ? f * __frsqrt_rn(f) : 0.0f;
        }
    }
}

extern "C" void kernel_launch(void* const* d_in, const int* in_sizes, int n_in,
                              void* d_out, int out_size) {
    const float* mask = (const float*)d_in[0];
    float* out = (float*)d_out;

    dim3 pgrid(C_DIM / 256, R_DIM / 32);   // (6, 48)
    pack_kernel<<<pgrid, 256>>>(mask);

    dim3 egrid(C_DIM / 256, W_DIM);        // (6, 48)
    edt_kernel<<<egrid, 256>>>(out);
}

// round 12
// speedup vs baseline: 1.5875x; 1.1484x over previous
#include <cuda_runtime.h>
#include <cuda_bf16.h>
#include <stdint.h>

// Exact Euclidean distance transform (matches the Meijster-style reference)
// on a 1536x1536 binary mask.
//
// Kernel 1 (pack): column-packed background bitmap via warp ballot transpose
//   into a zero-PADDED array (4 guard columns each side, 1 guard word-row
//   top/bottom). colbits[wi][j] bit b == (mask[(wi*32+b)*C + j] == 0).
//   Pads stay zero (device globals are zero-initialized; pack never writes
//   them), so out-of-image probes read "no background" with NO bounds checks.
//
// Kernel 2 (edt): 4 threads per (column, 32-row word); each owns 8 rows.
//   Bit-parallel 2D neighborhood search: all integer d^2 <= 9 levels
//   {0,1,2,4,5,8,9} computed for 32 rows at once from 17 bitmap words via
//   OR/funnel-shift (the quartet redundantly recomputes this cheap part, all
//   loads L1-hit), then each thread extracts/stores its own 8 rows -> 4x the
//   threads of the R11 version, which was occupancy-starved (occ 23%) because
//   the per-row epilogue dominated a single thread's work.
//   Rows with d^2 > 9 (P ~ 2^-29 per pixel for a random mask) fall to an
//   exact bitmap walk under a warp vote, reproducing the reference's
//   BIG = R+C cap. Exact for ANY input.
//
// All quantities (g^2 <= 3072^2, t^2, sums < 2^24) are integers exactly
// representable in fp32. sqrt via x*rsqrt(x) (error ~1e-7 << 1e-3 tol).

#define R_DIM 1536
#define C_DIM 1536
#define W_DIM (R_DIM / 32)          // 48 word-rows
#define BIG_I (R_DIM + C_DIM)       // 3072
#define CPAD  (C_DIM + 8)           // 4 guard cols each side
#define NROWS (W_DIM + 2)           // 1 guard word-row top/bottom

__device__ uint32_t g_colbits[NROWS * CPAD];   // zero-initialized; pads stay 0

__device__ __forceinline__ const uint32_t* cb_at(int wi, int j) {
    return &g_colbits[(wi + 1) * CPAD + 4 + j];
}

// 8 warps/block, each warp packs one 32x32 tile. grid(6, 48).
__global__ __launch_bounds__(256) void pack_kernel(const float* __restrict__ mask)
{
    const int lane = threadIdx.x & 31;
    const int warp = threadIdx.x >> 5;
    const int col0 = (blockIdx.x * 8 + warp) * 32;
    const int row0 = blockIdx.y * 32;

    const float* p = mask + row0 * C_DIM + col0 + lane;

    float v[32];
    #pragma unroll
    for (int r = 0; r < 32; ++r) v[r] = p[r * C_DIM];

    uint32_t myword = 0;
    #pragma unroll
    for (int r = 0; r < 32; ++r) {
        const uint32_t b = __ballot_sync(0xffffffffu, v[r] == 0.0f);
        myword |= ((b >> lane) & 1u) << r;
    }
    g_colbits[(blockIdx.y + 1) * CPAD + 4 + col0 + lane] = myword;
}

// Exact vertical distance^2 at (r, k) from the bitmap (rare path).
__device__ __noinline__ int g2_global(int r, int k)
{
    const int wi = r >> 5, bi = r & 31;
    const uint32_t w = *cb_at(wi, k);
    int best = BIG_I;
    const uint32_t dn = w >> bi;
    if (dn) best = __ffs(dn) - 1;
    const uint32_t up = w << (31 - bi);
    if (up) best = min(best, __clz(up));
    int wd = wi + 1, dn_off = 32 - bi;
    int wu = wi - 1, up_off = bi + 1;
    while ((wd < W_DIM && dn_off < best) || (wu >= 0 && up_off < best)) {
        if (wd < W_DIM && dn_off < best) {
            const uint32_t x = *cb_at(wd, k);
            if (x) best = min(best, dn_off + __ffs(x) - 1);
            ++wd; dn_off += 32;
        } else wd = W_DIM;
        if (wu >= 0 && up_off < best) {
            const uint32_t x = *cb_at(wu, k);
            if (x) best = min(best, up_off + __clz(x));
            --wu; up_off += 32;
        } else wu = -1;
    }
    return best * best;
}

// vertical +/-k shift across word boundaries: bit b set if (row +- k) set
__device__ __forceinline__ uint32_t sv(uint32_t w, uint32_t prev, uint32_t next, int k)
{
    return __funnelshift_r(w, next, k) | __funnelshift_l(prev, w, k);
}

// 256 threads = 64 columns x 4 row-quarters. grid(24, 48).
__global__ __launch_bounds__(256) void edt_kernel(float* __restrict__ out)
{
    const int tid = threadIdx.x;
    const int j   = blockIdx.x * 64 + (tid & 63);
    const int q   = tid >> 6;            // row-quarter 0..3
    const int sh  = q * 8;
    const int wi  = blockIdx.y;

    const uint32_t* W = cb_at(wi, j);
    const uint32_t* P = W - CPAD;
    const uint32_t* N = W + CPAD;

    // 17 word loads (pads make all of them branch-free; L1-hit, shared by quartet)
    const uint32_t c0 = W[0];
    const uint32_t c1 = W[-1] | W[1];
    const uint32_t c2 = W[-2] | W[2];
    const uint32_t c3 = W[-3] | W[3];
    const uint32_t p0 = P[0];
    const uint32_t p1 = P[-1] | P[1];
    const uint32_t p2 = P[-2] | P[2];
    const uint32_t n0 = N[0];
    const uint32_t n1 = N[-1] | N[1];
    const uint32_t n2 = N[-2] | N[2];

    // coverage masks per d^2 level (32 rows at once)
    const uint32_t D1 = sv(c0, p0, n0, 1) | c1;
    const uint32_t D2 = sv(c1, p1, n1, 1);
    const uint32_t D4 = sv(c0, p0, n0, 2) | c2;
    const uint32_t D5 = sv(c1, p1, n1, 2) | sv(c2, p2, n2, 1);
    const uint32_t D8 = sv(c2, p2, n2, 2);
    const uint32_t D9 = sv(c0, p0, n0, 3) | c3;

    // priority-exclusive masks -> 4 bit-planes of d^2
    uint32_t cum = c0;
    const uint32_t E1 = D1 & ~cum;  cum |= D1;
    const uint32_t E2 = D2 & ~cum;  cum |= D2;
    const uint32_t E4 = D4 & ~cum;  cum |= D4;
    const uint32_t E5 = D5 & ~cum;  cum |= D5;
    const uint32_t E8 = D8 & ~cum;  cum |= D8;
    const uint32_t E9 = D9 & ~cum;  cum |= D9;

    // shift planes so this thread's 8 rows sit in bits 0..7
    const uint32_t P0 = (E1 | E5 | E9) >> sh;   // d^2 bit0
    const uint32_t P1 = E2 >> sh;               // d^2 bit1
    const uint32_t P2 = (E4 | E5) >> sh;        // d^2 bit2
    const uint32_t P3 = (E8 | E9) >> sh;        // d^2 bit3

    float* orow = out + (wi * 32 + sh) * C_DIM + j;
    #pragma unroll
    for (int r = 0; r < 8; ++r) {
        const int d2 = ((P0 >> r) & 1) | (((P1 >> r) & 1) << 1)
                     | (((P2 >> r) & 1) << 2) | (((P3 >> r) & 1) << 3);
        const float f = (float)d2;
        orow[r * C_DIM] = d2 ? f * __frsqrt_rn(f) : 0.0f;
    }

    // exact fallback for rows with d^2 > 9 (essentially never taken)
    uint32_t uncov = (~cum >> sh) & 0xffu;
    if (__any_sync(0xffffffffu, uncov != 0u)) {
        while (uncov) {
            const int b = __ffs(uncov) - 1;
            uncov &= uncov - 1;
            const int row = wi * 32 + sh + b;
            int best = g2_global(row, j);
            int t = 1, t2 = 1, inc = 3;
            while (t2 < best) {
                const int kl = j - t, kr = j + t;
                if (kl < 0 && kr >= C_DIM) break;
                if (kl >= 0)     best = min(best, g2_global(row, kl) + t2);
                if (kr < C_DIM)  best = min(best, g2_global(row, kr) + t2);
                t2 += inc; inc += 2; ++t;
            }
            const float f = (float)best;
            orow[b * C_DIM] = best ? f * __frsqrt_rn(f) : 0.0f;
        }
    }
}

extern "C" void kernel_launch(void* const* d_in, const int* in_sizes, int n_in,
                              void* d_out, int out_size) {
    const float* mask = (const float*)d_in[0];
    float* out = (float*)d_out;

    dim3 pgrid(C_DIM / 256, R_DIM / 32);   // (6, 48)
    pack_kernel<<<pgrid, 256>>>(mask);

    dim3 egrid(C_DIM / 64, W_DIM);         // (24, 48)
    edt_kernel<<<egrid, 256>>>(out);
}

// round 13
// speedup vs baseline: 1.6563x; 1.0433x over previous
#include <cuda_runtime.h>
#include <cuda_bf16.h>
#include <stdint.h>

// Exact Euclidean distance transform (matches the Meijster-style reference)
// on a 1536x1536 binary mask.
//
// Kernel 1 (pack): column-packed background bitmap via warp ballot transpose
//   into a zero-PADDED array (4 guard cols each side, 1 guard word-row
//   top/bottom). colbits[wi][j] bit b == (mask[(wi*32+b)*C + j] == 0).
//   Pads stay zero -> out-of-image probes read "no background", no bounds checks.
//
// Kernel 2 (edt): block = 64 columns x one 32-row word, 256 threads.
//   Stage A (warps 0-1, one thread per column): bit-parallel coverage masks
//     for d^2 levels {1,2,4,5} from 15 bitmap words via OR/funnel-shift;
//     priority-exclusive encode into 3 bit-planes (d^2 <= 5 fits 3 bits;
//     uncovered rows forced to index 7). One uint4 STS per column.
//   Stage B (all 256 threads, 4 row-quarters x 64 cols): read planes from
//     smem, per row build 3-bit index, look up sqrt in an 8-entry smem LUT,
//     store. No I2F/RSQ/FMUL per pixel.
//   Rows with d^2 > 5 (P = 2^-21 per pixel for a random mask, ~1 px/image)
//   fall to an exact bitmap walk under a warp vote, reproducing the
//   reference's BIG = R+C cap. Exact for ANY input.
//
// All quantities (g^2 <= 3072^2, t^2, sums < 2^24) are integers exactly
// representable in fp32.

#define R_DIM 1536
#define C_DIM 1536
#define W_DIM (R_DIM / 32)          // 48 word-rows
#define BIG_I (R_DIM + C_DIM)       // 3072
#define CPAD  (C_DIM + 8)           // 4 guard cols each side
#define NROWS (W_DIM + 2)           // 1 guard word-row top/bottom

__device__ uint32_t g_colbits[NROWS * CPAD];   // zero-initialized; pads stay 0

__device__ __forceinline__ const uint32_t* cb_at(int wi, int j) {
    return &g_colbits[(wi + 1) * CPAD + 4 + j];
}

// 8 warps/block, each warp packs one 32x32 tile. grid(6, 48).
__global__ __launch_bounds__(256) void pack_kernel(const float* __restrict__ mask)
{
    const int lane = threadIdx.x & 31;
    const int warp = threadIdx.x >> 5;
    const int col0 = (blockIdx.x * 8 + warp) * 32;
    const int row0 = blockIdx.y * 32;

    const float* p = mask + row0 * C_DIM + col0 + lane;

    float v[32];
    #pragma unroll
    for (int r = 0; r < 32; ++r) v[r] = p[r * C_DIM];

    uint32_t myword = 0;
    #pragma unroll
    for (int r = 0; r < 32; ++r) {
        const uint32_t b = __ballot_sync(0xffffffffu, v[r] == 0.0f);
        myword |= ((b >> lane) & 1u) << r;
    }
    g_colbits[(blockIdx.y + 1) * CPAD + 4 + col0 + lane] = myword;
}

// Exact vertical distance^2 at (r, k) from the bitmap (rare path).
__device__ __noinline__ int g2_global(int r, int k)
{
    const int wi = r >> 5, bi = r & 31;
    const uint32_t w = *cb_at(wi, k);
    int best = BIG_I;
    const uint32_t dn = w >> bi;
    if (dn) best = __ffs(dn) - 1;
    const uint32_t up = w << (31 - bi);
    if (up) best = min(best, __clz(up));
    int wd = wi + 1, dn_off = 32 - bi;
    int wu = wi - 1, up_off = bi + 1;
    while ((wd < W_DIM && dn_off < best) || (wu >= 0 && up_off < best)) {
        if (wd < W_DIM && dn_off < best) {
            const uint32_t x = *cb_at(wd, k);
            if (x) best = min(best, dn_off + __ffs(x) - 1);
            ++wd; dn_off += 32;
        } else wd = W_DIM;
        if (wu >= 0 && up_off < best) {
            const uint32_t x = *cb_at(wu, k);
            if (x) best = min(best, up_off + __clz(x));
            --wu; up_off += 32;
        } else wu = -1;
    }
    return best * best;
}

// vertical +/-k shift across word boundaries: bit b set if (row +- k) set
__device__ __forceinline__ uint32_t sv(uint32_t w, uint32_t prev, uint32_t next, int k)
{
    return __funnelshift_r(w, next, k) | __funnelshift_l(prev, w, k);
}

// 256 threads = 64 columns x 4 row-quarters. grid(24, 48).
__global__ __launch_bounds__(256) void edt_kernel(float* __restrict__ out)
{
    const int tid = threadIdx.x;
    const int c   = tid & 63;
    const int q   = tid >> 6;            // row-quarter 0..3
    const int wi  = blockIdx.y;
    const int c0b = blockIdx.x * 64;
    const int j   = c0b + c;

    __shared__ uint4 planes[64];
    __shared__ float lut[8];

    if (tid < 8) {
        // index = P0 | P1<<1 | P2<<2; reachable: 0,1,2,4,5 (7 = uncovered)
        const float l[8] = {0.0f, 1.0f, 1.41421356f, 0.0f,
                            2.0f, 2.23606798f, 0.0f, 0.0f};
        lut[tid] = l[tid];
    }

    if (tid < 64) {
        const uint32_t* W = cb_at(wi, j);
        const uint32_t* P = W - CPAD;
        const uint32_t* N = W + CPAD;

        // 15 word loads (pads make all of them branch-free)
        const uint32_t c0 = W[0];
        const uint32_t c1 = W[-1] | W[1];
        const uint32_t c2 = W[-2] | W[2];
        const uint32_t p0 = P[0];
        const uint32_t p1 = P[-1] | P[1];
        const uint32_t p2 = P[-2] | P[2];
        const uint32_t n0 = N[0];
        const uint32_t n1 = N[-1] | N[1];
        const uint32_t n2 = N[-2] | N[2];

        // coverage masks per d^2 level (32 rows at once)
        const uint32_t D1 = sv(c0, p0, n0, 1) | c1;
        const uint32_t D2 = sv(c1, p1, n1, 1);
        const uint32_t D4 = sv(c0, p0, n0, 2) | c2;
        const uint32_t D5 = sv(c1, p1, n1, 2) | sv(c2, p2, n2, 1);

        // priority-exclusive -> 3 bit-planes; uncovered rows -> index 7
        uint32_t cum = c0;
        const uint32_t E1 = D1 & ~cum;  cum |= D1;
        const uint32_t E2 = D2 & ~cum;  cum |= D2;
        const uint32_t E4 = D4 & ~cum;  cum |= D4;
        const uint32_t E5 = D5 & ~cum;  cum |= D5;
        const uint32_t un = ~cum;

        uint4 pl;
        pl.x = E1 | E5 | un;            // bit0
        pl.y = E2 | un;                 // bit1
        pl.z = E4 | E5 | un;            // bit2
        pl.w = 0;
        planes[c] = pl;
    }

    __syncthreads();

    const uint4 pl = planes[c];
    const int sh = q * 8;
    const uint32_t b0 = pl.x >> sh;
    const uint32_t b1 = pl.y >> sh;
    const uint32_t b2 = pl.z >> sh;

    float* orow = out + (wi * 32 + sh) * C_DIM + j;
    #pragma unroll
    for (int r = 0; r < 8; ++r) {
        const int idx = ((b0 >> r) & 1) | (((b1 >> r) & 1) << 1)
                      | (((b2 >> r) & 1) << 2);
        orow[r * C_DIM] = lut[idx];
    }

    // exact fallback for rows with d^2 > 5 (~1 pixel per image)
    const uint32_t uncov8 = b0 & b1 & b2 & 0xffu;
    if (__any_sync(0xffffffffu, uncov8 != 0u)) {
        uint32_t uncov = uncov8;
        while (uncov) {
            const int b = __ffs(uncov) - 1;
            uncov &= uncov - 1;
            const int row = wi * 32 + sh + b;
            int best = g2_global(row, j);
            int t = 1, t2 = 1, inc = 3;
            while (t2 < best) {
                const int kl = j - t, kr = j + t;
                if (kl < 0 && kr >= C_DIM) break;
                if (kl >= 0)     best = min(best, g2_global(row, kl) + t2);
                if (kr < C_DIM)  best = min(best, g2_global(row, kr) + t2);
                t2 += inc; inc += 2; ++t;
            }
            const float f = (float)best;
            orow[b * C_DIM] = best ? f * __frsqrt_rn(f) : 0.0f;
        }
    }
}

extern "C" void kernel_launch(void* const* d_in, const int* in_sizes, int n_in,
                              void* d_out, int out_size) {
    const float* mask = (const float*)d_in[0];
    float* out = (float*)d_out;

    dim3 pgrid(C_DIM / 256, R_DIM / 32);   // (6, 48)
    pack_kernel<<<pgrid, 256>>>(mask);

    dim3 egrid(C_DIM / 64, W_DIM);         // (24, 48)
    edt_kernel<<<egrid, 256>>>(out);
}